// round 3
// baseline (speedup 1.0000x reference)
#include <cuda_runtime.h>
#include <cstdint>

#define DIAM   1024
#define NPIX   (DIAM * DIAM)
#define N_WL   31
#define NEL    (NPIX * N_WL)        // 32,505,856
#define NQ     (NEL / 4)            // 8,126,464 float4 quads
#define RADIUS 512

// Accurate sincos for |x| < ~3e4 via 2-step FMA Cody-Waite reduction.
// Immune to fast-math flag remapping; abs error ~1e-7 (vs 1e-3 tolerance).
__device__ __forceinline__ void my_sincos(float x, float& s_out, float& c_out) {
    float j = rintf(__fmul_rn(x, 0.63661977236758134f));   // x * 2/pi
    int   qi = (int)j;
    // r = x - j*pi/2, pi/2 = h1 + h2 (h1 = fp32(pi/2), h2 = fp32(pi/2 - h1))
    float r = fmaf(j, -1.5707963705062866e+00f, x);
    r       = fmaf(j,  4.3711390001862449e-08f, r);        // subtract j*h2 (h2 < 0)
    float z = r * r;
    // sin poly on [-pi/4, pi/4]
    float sp = fmaf(z, -1.9515295891e-4f, 8.3321608736e-3f);
    sp       = fmaf(z, sp, -1.6666654611e-1f);
    float sr = fmaf(r * z, sp, r);
    // cos poly
    float cp = fmaf(z, 2.443315711809948e-5f, -1.388731625493765e-3f);
    cp       = fmaf(z, cp, 4.166664568298827e-2f);
    float cr = fmaf(z * z, cp, fmaf(z, -0.5f, 1.0f));
    bool odd = (qi & 1);
    float ss = odd ? cr : sr;
    float cc = odd ? sr : cr;
    if (qi & 2)       ss = -ss;
    if ((qi + 1) & 2) cc = -cc;
    s_out = ss;
    c_out = cc;
}

__global__ __launch_bounds__(256)
void doe_kernel(const float* __restrict__ hw,      // height_map_weight [512]
                const float* __restrict__ fr,      // field_real  [NEL]
                const float* __restrict__ fi,      // field_imag  [NEL]
                const float* __restrict__ wl,      // wavelength  [31]
                const float* __restrict__ noise,   // noise       [NPIX]
                const float* __restrict__ rad,     // radius_distance [NPIX]
                float* __restrict__ out)           // [2 * NEL]
{
    __shared__ float s_table[512];
    __shared__ float s_t[N_WL];   // k * delta_n per wavelength

    // q_base_height = lam0 / (n(lam0) - 1), replicated with exact fp32 rounding
    const float lam0 = 7e-07f;
    float n0 = __fadd_rn(1.5f, __fdiv_rn(4e-15f, __fmul_rn(lam0, lam0)));
    float qh = __fdiv_rn(lam0, __fsub_rn(n0, 1.0f));

    for (int i = threadIdx.x; i < 512; i += blockDim.x) {
        float w = hw[i];
        w = fminf(fmaxf(w, -1.0f), 1.0f);
        float normed = __fmul_rn(__fadd_rn(w, 1.0f), 0.5f);
        s_table[i] = __fsub_rn(0.002f, __fmul_rn(qh, normed));
    }
    if (threadIdx.x < N_WL) {
        float l  = wl[threadIdx.x];
        float k  = __fdiv_rn(6.283185307179586f, l);
        float dn = __fsub_rn(__fadd_rn(1.5f, __fdiv_rn(4e-15f, __fmul_rn(l, l))), 1.0f);
        s_t[threadIdx.x] = __fmul_rn(k, dn);
    }
    __syncthreads();

    const float4* fr4p = (const float4*)fr;
    const float4* fi4p = (const float4*)fi;
    float4* out_r = (float4*)out;
    float4* out_i = (float4*)out + NQ;

    for (int q = blockIdx.x * blockDim.x + threadIdx.x; q < NQ;
         q += gridDim.x * blockDim.x) {
        int e = q * 4;
        unsigned p  = (unsigned)e / 31u;
        int      w0 = e - (int)(p * 31u);
        bool cross  = (w0 > 27);              // quad straddles pixel boundary
        unsigned pB = cross ? (p + 1u) : p;

        float rA = rad[p];
        float rB = rad[pB];
        bool inA = (rA <= (float)RADIUS);
        bool inB = (rB <= (float)RADIUS);

        if (!inA && !inB) {
            // outside aperture: output exactly zero, skip field loads + math
            float4 z4 = make_float4(0.f, 0.f, 0.f, 0.f);
            out_r[q] = z4;
            out_i[q] = z4;
            continue;
        }

        // hmap per pixel (exact fp32 rounding of table[idx] + noise)
        int idxA = min(max((int)ceilf(rA) - 1, 0), 511);
        int idxB = min(max((int)ceilf(rB) - 1, 0), 511);
        float hA = __fadd_rn(inA ? s_table[idxA] : 0.0f, noise[p]);
        float hB = __fadd_rn(inB ? s_table[idxB] : 0.0f, noise[pB]);

        float4 f_r = fr4p[q];
        float4 f_i = fi4p[q];
        float frv[4] = {f_r.x, f_r.y, f_r.z, f_r.w};
        float fiv[4] = {f_i.x, f_i.y, f_i.z, f_i.w};
        float orv[4], oiv[4];

        #pragma unroll
        for (int k4 = 0; k4 < 4; k4++) {
            int  wli    = w0 + k4;
            bool second = (wli >= N_WL);
            int  wlm    = second ? (wli - N_WL) : wli;
            float h     = second ? hB : hA;
            bool  in    = second ? inB : inA;
            float phase = __fmul_rn(s_t[wlm], h);
            float s, c;
            my_sincos(phase, s, c);
            float orr = __fsub_rn(__fmul_rn(frv[k4], c), __fmul_rn(fiv[k4], s));
            float oii = __fadd_rn(__fmul_rn(frv[k4], s), __fmul_rn(fiv[k4], c));
            orv[k4] = in ? orr : 0.0f;
            oiv[k4] = in ? oii : 0.0f;
        }

        out_r[q] = make_float4(orv[0], orv[1], orv[2], orv[3]);
        out_i[q] = make_float4(oiv[0], oiv[1], oiv[2], oiv[3]);
    }
}

extern "C" void kernel_launch(void* const* d_in, const int* in_sizes, int n_in,
                              void* d_out, int out_size) {
    const float* hw    = (const float*)d_in[0];  // height_map_weight
    const float* fr    = (const float*)d_in[1];  // field_real
    const float* fi    = (const float*)d_in[2];  // field_imag
    const float* wl    = (const float*)d_in[3];  // wavelength
    const float* noise = (const float*)d_in[4];  // noise
    const float* rad   = (const float*)d_in[5];  // radius_distance
    // d_in[6] aperture: identical to (rad <= 512), recomputed in-kernel

    doe_kernel<<<4736, 256>>>(hw, fr, fi, wl, noise, rad, (float*)d_out);
}